// round 12
// baseline (speedup 1.0000x reference)
#include <cuda_runtime.h>
#include <cuda_fp16.h>
#include <math.h>
#include <stdint.h>

// ---------------------------------------------------------------------------
// Problem constants
// ---------------------------------------------------------------------------
#define Bb   4
#define Tt   1024
#define Dd   1024
#define Hh   16
#define DK   64
#define DV   64
#define II   2816
#define EPSf 1e-6f
#define ROWS (Bb*Tt)              // 4096

// ---------------------------------------------------------------------------
// Scratch (static device memory; no allocations allowed)
// ---------------------------------------------------------------------------
__device__ float g_h   [ROWS*Dd];
__device__ float g_qpre[ROWS*Dd];
__device__ float g_kpre[ROWS*Dd];
__device__ float g_vpre[ROWS*Dd];
__device__ float g_q   [ROWS*Dd];
__device__ float g_k   [ROWS*Dd];
__device__ float g_v   [ROWS*Dd];
__device__ float g_beta[ROWS*Hh];
__device__ float g_g   [ROWS*Hh];
__device__ float g_o   [ROWS*Dd];
__device__ float g_h2  [ROWS*Dd];
__device__ float g_h3  [ROWS*Dd];
__device__ float g_gy  [ROWS*2*II];
__device__ float g_act [ROWS*II];

// ---------------------------------------------------------------------------
// RMSNorm over D=1024, one block (256 thr) per row
// ---------------------------------------------------------------------------
__global__ void rmsnorm_kernel(const float* __restrict__ x, const float* __restrict__ w,
                               float* __restrict__ out) {
    int row = blockIdx.x;
    const float4* xr = (const float4*)(x + (size_t)row * Dd);
    float4 v = xr[threadIdx.x];
    float ss = v.x*v.x + v.y*v.y + v.z*v.z + v.w*v.w;
    #pragma unroll
    for (int m = 16; m >= 1; m >>= 1) ss += __shfl_xor_sync(0xffffffffu, ss, m);
    __shared__ float wsum[8];
    if ((threadIdx.x & 31) == 0) wsum[threadIdx.x >> 5] = ss;
    __syncthreads();
    float tot = wsum[0]+wsum[1]+wsum[2]+wsum[3]+wsum[4]+wsum[5]+wsum[6]+wsum[7];
    float r = rsqrtf(tot * (1.0f/Dd) + EPSf);
    float4 wv = ((const float4*)w)[threadIdx.x];
    float4 o;
    o.x = v.x*r*wv.x; o.y = v.y*r*wv.y; o.z = v.z*r*wv.z; o.w = v.w*r*wv.w;
    ((float4*)(out + (size_t)row * Dd))[threadIdx.x] = o;
}

// ---------------------------------------------------------------------------
// FP16 tensor-core GEMM: C[M,N] = A[M,K] @ B[K,N] (+addsrc), fp32 accumulate.
// BM=128 BN=128 BK=32, 256 threads (8 warps, 2x4), warp tile 64x32,
// mma.sync.m16n8k16.f16, ldmatrix (A: x4, B: x4.trans), double-buffered smem.
// ---------------------------------------------------------------------------
#define GBM 128
#define GBN 128
#define GBK 32
#define A_ROW_H 40
#define B_ROW_H 136

__device__ __forceinline__ uint32_t h2u(__half2 h) { return *(uint32_t*)&h; }

__device__ __forceinline__ void mma_f16(float& c0, float& c1, float& c2, float& c3,
                                        uint32_t a0, uint32_t a1, uint32_t a2, uint32_t a3,
                                        uint32_t b0, uint32_t b1) {
    asm volatile(
        "mma.sync.aligned.m16n8k16.row.col.f32.f16.f16.f32 "
        "{%0,%1,%2,%3}, {%4,%5,%6,%7}, {%8,%9}, {%0,%1,%2,%3};"
        : "+f"(c0), "+f"(c1), "+f"(c2), "+f"(c3)
        : "r"(a0), "r"(a1), "r"(a2), "r"(a3), "r"(b0), "r"(b1));
}

__device__ __forceinline__ void ldsm_x4(uint32_t* r, uint32_t addr) {
    asm volatile("ldmatrix.sync.aligned.m8n8.x4.shared.b16 {%0,%1,%2,%3}, [%4];"
                 : "=r"(r[0]), "=r"(r[1]), "=r"(r[2]), "=r"(r[3]) : "r"(addr));
}
__device__ __forceinline__ void ldsm_x4t(uint32_t* r, uint32_t addr) {
    asm volatile("ldmatrix.sync.aligned.m8n8.x4.trans.shared.b16 {%0,%1,%2,%3}, [%4];"
                 : "=r"(r[0]), "=r"(r[1]), "=r"(r[2]), "=r"(r[3]) : "r"(addr));
}

__device__ __forceinline__ void cvt_f4_h2(const float4& v, uint2& o) {
    __half2 p0 = __floats2half2_rn(v.x, v.y);
    __half2 p1 = __floats2half2_rn(v.z, v.w);
    o.x = h2u(p0); o.y = h2u(p1);
}

__device__ __forceinline__ void mma_gemm_body(
    const float* __restrict__ A, const float* __restrict__ B,
    const float* __restrict__ addsrc, float* __restrict__ C,
    int N, int Kd, int bm, int bn) {
    __shared__ __align__(16) __half As[2][128*A_ROW_H];
    __shared__ __align__(16) __half Bs[2][32*B_ROW_H];

    int tid = threadIdx.x;
    int lane = tid & 31;
    int w    = tid >> 5;
    int lq = lane >> 2;
    int lr = lane & 3;
    int wm = w >> 2;
    int wn = w & 3;

    int a_row = tid >> 1;
    int a_h16 = tid & 1;
    const float* Ag = A + (size_t)(bm + a_row) * Kd + a_h16*16;
    int a_soff = a_row*A_ROW_H + a_h16*16;

    int b_k  = tid >> 3;
    int b_n0 = (tid & 7) * 16;
    const float* Bg = B + (size_t)b_k * N + bn + b_n0;
    int b_soff = b_k*B_ROW_H + b_n0;

    float acc[4][4][4];
    #pragma unroll
    for (int mi = 0; mi < 4; mi++)
        #pragma unroll
        for (int ni = 0; ni < 4; ni++)
            #pragma unroll
            for (int r = 0; r < 4; r++) acc[mi][ni][r] = 0.0f;

    int nch = Kd / GBK;

    uint2 arh[4], brh[4];
    #pragma unroll
    for (int i = 0; i < 4; i++) { cvt_f4_h2(*(const float4*)(Ag + 4*i), arh[i]); }
    #pragma unroll
    for (int i = 0; i < 4; i++) { cvt_f4_h2(*(const float4*)(Bg + 4*i), brh[i]); }

    #pragma unroll
    for (int i = 0; i < 4; i++) {
        *(uint2*)&As[0][a_soff + 4*i] = arh[i];
        *(uint2*)&Bs[0][b_soff + 4*i] = brh[i];
    }
    __syncthreads();

    for (int ch = 0; ch < nch; ch++) {
        int s = ch & 1;
        if (ch + 1 < nch) {
            const float* Agn = Ag + (ch + 1) * GBK;
            const float* Bgn = Bg + (size_t)(ch + 1) * GBK * N;
            #pragma unroll
            for (int i = 0; i < 4; i++) cvt_f4_h2(*(const float4*)(Agn + 4*i), arh[i]);
            #pragma unroll
            for (int i = 0; i < 4; i++) cvt_f4_h2(*(const float4*)(Bgn + 4*i), brh[i]);
        }

        #pragma unroll
        for (int ksi = 0; ksi < 2; ksi++) {
            uint32_t af[4][4];
            #pragma unroll
            for (int mi = 0; mi < 4; mi++) {
                int r = wm*64 + mi*16 + (lane & 15);
                uint32_t ad = (uint32_t)__cvta_generic_to_shared(
                    &As[s][r*A_ROW_H + ksi*16 + (lane >> 4)*8]);
                ldsm_x4(af[mi], ad);
            }
            // B: x4.trans loads two adjacent n8 fragments at once
            uint32_t bf[4][2];
            #pragma unroll
            for (int ni8 = 0; ni8 < 2; ni8++) {
                int kr = ksi*16 + (lane & 15);
                uint32_t ad = (uint32_t)__cvta_generic_to_shared(
                    &Bs[s][kr*B_ROW_H + wn*32 + ni8*16 + (lane >> 4)*8]);
                uint32_t tmp[4];
                ldsm_x4t(tmp, ad);
                bf[2*ni8  ][0] = tmp[0]; bf[2*ni8  ][1] = tmp[1];
                bf[2*ni8+1][0] = tmp[2]; bf[2*ni8+1][1] = tmp[3];
            }
            #pragma unroll
            for (int mi = 0; mi < 4; mi++)
                #pragma unroll
                for (int ni = 0; ni < 4; ni++)
                    mma_f16(acc[mi][ni][0], acc[mi][ni][1], acc[mi][ni][2], acc[mi][ni][3],
                            af[mi][0], af[mi][1], af[mi][2], af[mi][3],
                            bf[ni][0], bf[ni][1]);
        }

        if (ch + 1 < nch) {
            int s1 = s ^ 1;
            #pragma unroll
            for (int i = 0; i < 4; i++) {
                *(uint2*)&As[s1][a_soff + 4*i] = arh[i];
                *(uint2*)&Bs[s1][b_soff + 4*i] = brh[i];
            }
            __syncthreads();
        }
    }

    #pragma unroll
    for (int mi = 0; mi < 4; mi++) {
        int r0 = bm + wm*64 + mi*16 + lq;
        #pragma unroll
        for (int ni = 0; ni < 4; ni++) {
            int col = bn + wn*32 + ni*8 + 2*lr;
            float2 v0 = make_float2(acc[mi][ni][0], acc[mi][ni][1]);
            float2 v1 = make_float2(acc[mi][ni][2], acc[mi][ni][3]);
            if (addsrc) {
                float2 s0 = *(const float2*)(addsrc + (size_t)r0 * N + col);
                float2 s1 = *(const float2*)(addsrc + (size_t)(r0+8) * N + col);
                v0.x += s0.x; v0.y += s0.y; v1.x += s1.x; v1.y += s1.y;
            }
            *(float2*)(C + (size_t)r0 * N + col) = v0;
            *(float2*)(C + (size_t)(r0+8) * N + col) = v1;
        }
    }
}

__global__ __launch_bounds__(256, 2) void mma_gemm_kernel(
    const float* __restrict__ A, const float* __restrict__ B,
    const float* __restrict__ addsrc, float* __restrict__ C,
    int N, int Kd) {
    mma_gemm_body(A, B, addsrc, C, N, Kd, blockIdx.y * GBM, blockIdx.x * GBN);
}

__global__ __launch_bounds__(256, 2) void mma_gemm_qkv_kernel(
    const float* __restrict__ A,
    const float* __restrict__ B0, const float* __restrict__ B1, const float* __restrict__ B2,
    float* __restrict__ C0, float* __restrict__ C1, float* __restrict__ C2,
    int N, int Kd) {
    const float* B = (blockIdx.z == 0) ? B0 : ((blockIdx.z == 1) ? B1 : B2);
    float*       C = (blockIdx.z == 0) ? C0 : ((blockIdx.z == 1) ? C1 : C2);
    mma_gemm_body(A, B, nullptr, C, N, Kd, blockIdx.y * GBM, blockIdx.x * GBN);
}

// ---------------------------------------------------------------------------
// Fused causal depthwise conv1d (K=4) + SiLU + optional per-head L2 norm.
// ---------------------------------------------------------------------------
__global__ void conv_fused3_kernel(
    const float* __restrict__ xq, const float* __restrict__ wq, float* __restrict__ oq,
    const float* __restrict__ xk, const float* __restrict__ wk, float* __restrict__ ok,
    const float* __restrict__ xv, const float* __restrict__ wv, float* __restrict__ ov) {
    int which = blockIdx.y;
    const float* xin = (which == 0) ? xq : ((which == 1) ? xk : xv);
    const float* w   = (which == 0) ? wq : ((which == 1) ? wk : wv);
    float* out       = (which == 0) ? oq : ((which == 1) ? ok : ov);
    float scale = (which == 0) ? 0.125f : 1.0f;
    int do_l2   = (which != 2);

    int row = blockIdx.x;
    int t = row & (Tt - 1);
    int c4 = threadIdx.x * 4;
    size_t base = (size_t)row * Dd + c4;

    float4 x0 = *(const float4*)(xin + base);
    float4 x1 = (t >= 1) ? *(const float4*)(xin + base - Dd)   : make_float4(0,0,0,0);
    float4 x2 = (t >= 2) ? *(const float4*)(xin + base - 2*Dd) : make_float4(0,0,0,0);
    float4 x3 = (t >= 3) ? *(const float4*)(xin + base - 3*Dd) : make_float4(0,0,0,0);

    float y[4];
    #pragma unroll
    for (int j = 0; j < 4; j++) {
        float4 w4 = ((const float4*)w)[c4 + j];
        float a = (&x0.x)[j]*w4.w + (&x1.x)[j]*w4.z + (&x2.x)[j]*w4.y + (&x3.x)[j]*w4.x;
        y[j] = a / (1.0f + expf(-a));
    }

    if (do_l2) {
        float ss = y[0]*y[0] + y[1]*y[1] + y[2]*y[2] + y[3]*y[3];
        #pragma unroll
        for (int m = 8; m >= 1; m >>= 1) ss += __shfl_xor_sync(0xffffffffu, ss, m);
        float r = rsqrtf(ss + EPSf) * scale;
        #pragma unroll
        for (int j = 0; j < 4; j++) y[j] *= r;
    }
    *(float4*)(out + base) = make_float4(y[0], y[1], y[2], y[3]);
}

// ---------------------------------------------------------------------------
// Per-(b,t,h) RMSNorm over DV=64 with weight. In place.
// ---------------------------------------------------------------------------
__global__ void o_rmsnorm_kernel(float* __restrict__ o, const float* __restrict__ w) {
    int gidx = blockIdx.x * 8 + (threadIdx.x >> 5);
    int lane = threadIdx.x & 31;
    size_t base = (size_t)gidx * 64;
    float a = o[base + lane], b = o[base + 32 + lane];
    float ss = a*a + b*b;
    #pragma unroll
    for (int m = 16; m >= 1; m >>= 1) ss += __shfl_xor_sync(0xffffffffu, ss, m);
    float r = rsqrtf(ss * (1.0f/64.0f) + EPSf);
    o[base + lane]      = a * r * w[lane];
    o[base + 32 + lane] = b * r * w[lane + 32];
}

// ---------------------------------------------------------------------------
// beta / g projections v3 (R10 winner)
// ---------------------------------------------------------------------------
#define BETAG_BLOCKS 128
#define BETAG_RPB 32
#define BETAG_PASS 16
#define BETAG_SMEM_FLTS (2*Dd*Hh + BETAG_PASS*Dd)
#define BETAG_SMEM_BYTES (BETAG_SMEM_FLTS*4)

__global__ __launch_bounds__(256) void betag_kernel(
    const float* __restrict__ h,
    const float* __restrict__ Wb, const float* __restrict__ Wa,
    const float* __restrict__ dt_bias, const float* __restrict__ A_log,
    float* __restrict__ beta, float* __restrict__ g) {
    extern __shared__ float bsm[];
    float* wbs = bsm;
    float* was = bsm + Dd*Hh;
    float* hst = bsm + 2*Dd*Hh;

    int tid = threadIdx.x;
    int hh  = tid & 15;
    int grp = tid >> 4;
    int row0 = blockIdx.x * BETAG_RPB;

    for (int i = tid; i < 8192; i += 256) {
        float4 vb = ((const float4*)Wb)[i & 4095];
        if (i < 4096) ((float4*)wbs)[i] = vb;
        else          ((float4*)was)[i - 4096] = ((const float4*)Wa)[i - 4096];
    }

    for (int p = 0; p < 2; p++) {
        int prow0 = row0 + p * BETAG_PASS;
        __syncthreads();
        for (int i = tid; i < 4096; i += 256)
            ((float4*)hst)[i] = ((const float4*)(h + (size_t)prow0 * Dd))[i];
        __syncthreads();

        float sb[BETAG_PASS], sa[BETAG_PASS];
        #pragma unroll
        for (int r = 0; r < BETAG_PASS; r++) { sb[r] = 0.0f; sa[r] = 0.0f; }

        #pragma unroll 4
        for (int j = 0; j < 64; j++) {
            int d = j*16 + grp;
            float wb = wbs[d*Hh + hh];
            float wa = was[d*Hh + hh];
            #pragma unroll
            for (int r = 0; r < BETAG_PASS; r++) {
                float hv = hst[r*Dd + d];
                sb[r] += hv * wb;
                sa[r] += hv * wa;
            }
        }
        __syncthreads();

        #pragma unroll
        for (int r = 0; r < BETAG_PASS; r++) {
            hst[(r<<9) + (grp<<4) + hh]       = sb[r];
            hst[(r<<9) + 256 + (grp<<4) + hh] = sa[r];
        }
        __syncthreads();

        #pragma unroll
        for (int u = 0; u < 2; u++) {
            int idx = tid + u*256;
            int r2    = idx >> 5;
            int which = (idx >> 4) & 1;
            int hh2   = idx & 15;
            const float* rp = hst + (r2<<9) + which*256 + hh2;
            float s = 0.0f;
            #pragma unroll
            for (int gg2 = 0; gg2 < 16; gg2++) s += rp[gg2*16];
            int row = prow0 + r2;
            if (which == 0) {
                beta[row*Hh + hh2] = 2.0f / (1.0f + expf(-s));
            } else {
                float xg = s + dt_bias[hh2];
                float sp = (xg > 15.0f) ? xg : log1pf(expf(xg));
                g[row*Hh + hh2] = -expf(A_log[hh2]) * sp;
            }
        }
    }
}

// ---------------------------------------------------------------------------
// Gated delta-rule scan, column-split x2 (the scan is fma-ISSUE-bound: 512
// warp-instr/step at 2cyc/FMA-instr per SMSP -> splitting a chain across two
// SMs halves the issue floor). Grid (Hh, Bb, 2); 32 cols/block, 8 rows/thread.
// c_loc = tid>>3, sub = tid&7 (xor 1,2,4 stays in-warp, within 8-lane group).
// ---------------------------------------------------------------------------
__device__ __forceinline__ float scan_load(const float* __restrict__ q,
                                           const float* __restrict__ k,
                                           const float* __restrict__ v,
                                           const float* __restrict__ beta,
                                           const float* __restrict__ g,
                                           int b, int h, int t, int tid) {
    size_t off = ((size_t)(b*Tt + t)) * 1024 + h * 64;
    if (tid < 64)  return k[off + tid];
    if (tid < 128) return q[off + tid - 64];
    if (tid < 192) return v[off + tid - 128];
    if (tid == 192) return beta[(size_t)(b*Tt + t)*Hh + h];
    return g[(size_t)(b*Tt + t)*Hh + h];
}

__global__ __launch_bounds__(256) void scan_kernel(
    const float* __restrict__ q, const float* __restrict__ k, const float* __restrict__ v,
    const float* __restrict__ beta, const float* __restrict__ g,
    float* __restrict__ o, float* __restrict__ state_out) {
    int h = blockIdx.x, b = blockIdx.y, half = blockIdx.z;
    int tid = threadIdx.x;
    int c_loc = tid >> 3;            // 0..31
    int sub   = tid & 7;             // rows sub*8..sub*8+7
    int col   = half * 32 + c_loc;

    __shared__ __align__(16) float sh[2][200];

    float S[8];
    #pragma unroll
    for (int r = 0; r < 8; r++) S[r] = 0.0f;

    float rv = (tid < 194) ? scan_load(q, k, v, beta, g, b, h, 0, tid) : 0.0f;

    for (int t = 0; t < Tt; t++) {
        float* buf = sh[t & 1];
        if (tid < 194) buf[tid] = rv;
        __syncthreads();
        if (t + 1 < Tt && tid < 194)
            rv = scan_load(q, k, v, beta, g, b, h, t + 1, tid);

        float eg = expf(buf[193]);
        float bt = buf[192];

        const float4* kp4 = (const float4*)(buf + sub*8);
        const float4* qp4 = (const float4*)(buf + 64 + sub*8);
        float kr[8], qr[8];
        #pragma unroll
        for (int rr = 0; rr < 2; rr++) {
            float4 kv4 = kp4[rr];
            kr[rr*4+0] = kv4.x; kr[rr*4+1] = kv4.y; kr[rr*4+2] = kv4.z; kr[rr*4+3] = kv4.w;
            float4 qv4 = qp4[rr];
            qr[rr*4+0] = qv4.x; qr[rr*4+1] = qv4.y; qr[rr*4+2] = qv4.z; qr[rr*4+3] = qv4.w;
        }

        // 2 independent partial chains (8 rows)
        float k0 = 0.0f, k1 = 0.0f;
        #pragma unroll
        for (int r4 = 0; r4 < 4; r4++) {
            S[r4]   *= eg; k0 += kr[r4]   * S[r4];
            S[r4+4] *= eg; k1 += kr[r4+4] * S[r4+4];
        }
        float kvp = k0 + k1;
        kvp += __shfl_xor_sync(0xffffffffu, kvp, 1);
        kvp += __shfl_xor_sync(0xffffffffu, kvp, 2);
        kvp += __shfl_xor_sync(0xffffffffu, kvp, 4);

        float delta = (buf[128 + col] - kvp) * bt;

        float o0 = 0.0f, o1 = 0.0f;
        #pragma unroll
        for (int r4 = 0; r4 < 4; r4++) {
            S[r4]   += kr[r4]   * delta; o0 += qr[r4]   * S[r4];
            S[r4+4] += kr[r4+4] * delta; o1 += qr[r4+4] * S[r4+4];
        }
        float op = o0 + o1;
        op += __shfl_xor_sync(0xffffffffu, op, 1);
        op += __shfl_xor_sync(0xffffffffu, op, 2);
        op += __shfl_xor_sync(0xffffffffu, op, 4);
        if (sub == 0)
            o[((size_t)(b*Tt + t)*Hh + h) * DV + col] = op;
    }

    #pragma unroll
    for (int r = 0; r < 8; r++)
        state_out[((size_t)(b*Hh + h)*DK + sub*8 + r) * DV + col] = S[r];
}

// ---------------------------------------------------------------------------
// SwiGLU
// ---------------------------------------------------------------------------
__global__ void swiglu_kernel(const float* __restrict__ gy, float* __restrict__ act) {
    int idx = blockIdx.x * blockDim.x + threadIdx.x;
    int row = idx / II;
    int i   = idx - row * II;
    float gate = gy[(size_t)row * (2*II) + i];
    float y    = gy[(size_t)row * (2*II) + II + i];
    act[idx] = gate / (1.0f + expf(-gate)) * y;
}

// ---------------------------------------------------------------------------
// launch
// ---------------------------------------------------------------------------
extern "C" void kernel_launch(void* const* d_in, const int* in_sizes, int n_in,
                              void* d_out, int out_size) {
    const float* x           = (const float*)d_in[0];
    const float* attn_norm_w = (const float*)d_in[1];
    const float* Wq          = (const float*)d_in[2];
    const float* Wk          = (const float*)d_in[3];
    const float* Wv          = (const float*)d_in[4];
    const float* cq          = (const float*)d_in[5];
    const float* ck          = (const float*)d_in[6];
    const float* cv          = (const float*)d_in[7];
    const float* Wb          = (const float*)d_in[8];
    const float* Wa          = (const float*)d_in[9];
    const float* dt_bias     = (const float*)d_in[10];
    const float* A_log       = (const float*)d_in[11];
    const float* o_norm_w    = (const float*)d_in[12];
    const float* Wo          = (const float*)d_in[13];
    const float* mlp_norm_w  = (const float*)d_in[14];
    const float* Wg          = (const float*)d_in[15];
    const float* Wd          = (const float*)d_in[16];
    float* out = (float*)d_out;

    float *h, *qpre, *kpre, *vpre, *q, *k, *v, *beta, *gg, *o, *h2, *h3, *gy, *act;
    cudaGetSymbolAddress((void**)&h,    g_h);
    cudaGetSymbolAddress((void**)&qpre, g_qpre);
    cudaGetSymbolAddress((void**)&kpre, g_kpre);
    cudaGetSymbolAddress((void**)&vpre, g_vpre);
    cudaGetSymbolAddress((void**)&q,    g_q);
    cudaGetSymbolAddress((void**)&k,    g_k);
    cudaGetSymbolAddress((void**)&v,    g_v);
    cudaGetSymbolAddress((void**)&beta, g_beta);
    cudaGetSymbolAddress((void**)&gg,   g_g);
    cudaGetSymbolAddress((void**)&o,    g_o);
    cudaGetSymbolAddress((void**)&h2,   g_h2);
    cudaGetSymbolAddress((void**)&h3,   g_h3);
    cudaGetSymbolAddress((void**)&gy,   g_gy);
    cudaGetSymbolAddress((void**)&act,  g_act);

    cudaFuncSetAttribute(betag_kernel,
                         cudaFuncAttributeMaxDynamicSharedMemorySize, BETAG_SMEM_BYTES);

    // 1. h = rmsnorm(x)
    rmsnorm_kernel<<<ROWS, 256>>>(x, attn_norm_w, h);

    // 2. q/k/v projections
    dim3 gqkv(Dd/GBN, ROWS/GBM, 3);
    mma_gemm_qkv_kernel<<<gqkv, 256>>>(h, Wq, Wk, Wv, qpre, kpre, vpre, Dd, Dd);

    // 3. conv + silu (+ fused l2norm for q,k)
    conv_fused3_kernel<<<dim3(ROWS, 3), 256>>>(qpre, cq, q, kpre, ck, k, vpre, cv, v);

    // 4. beta / g
    betag_kernel<<<BETAG_BLOCKS, 256, BETAG_SMEM_BYTES>>>(h, Wb, Wa, dt_bias, A_log, beta, gg);

    // 5. delta-rule scan (column-split x2)
    scan_kernel<<<dim3(Hh, Bb, 2), 256>>>(q, k, v, beta, gg, o, out + (size_t)ROWS*Dd);

    // 6. per-head output RMSNorm
    o_rmsnorm_kernel<<<(ROWS*Hh)/8, 256>>>(o, o_norm_w);

    // 7. attn projection + residual
    dim3 g1024(Dd/GBN, ROWS/GBM);
    mma_gemm_kernel<<<g1024, 256>>>(o, Wo, x, h2, Dd, Dd);

    // 8. MLP
    rmsnorm_kernel<<<ROWS, 256>>>(h2, mlp_norm_w, h3);
    dim3 gwg((2*II)/GBN, ROWS/GBM);
    mma_gemm_kernel<<<gwg, 256>>>(h3, Wg, nullptr, gy, 2*II, Dd);
    swiglu_kernel<<<(ROWS*II)/256, 256>>>(gy, act);
    mma_gemm_kernel<<<g1024, 256>>>(act, Wd, h2, out, Dd, II);
}

// round 13
// speedup vs baseline: 1.6231x; 1.6231x over previous
#include <cuda_runtime.h>
#include <cuda_fp16.h>
#include <math.h>
#include <stdint.h>

// ---------------------------------------------------------------------------
// Problem constants
// ---------------------------------------------------------------------------
#define Bb   4
#define Tt   1024
#define Dd   1024
#define Hh   16
#define DK   64
#define DV   64
#define II   2816
#define EPSf 1e-6f
#define ROWS (Bb*Tt)              // 4096

// ---------------------------------------------------------------------------
// Scratch (static device memory; no allocations allowed)
// ---------------------------------------------------------------------------
__device__ float  g_h   [ROWS*Dd];      // rmsnorm(x), fp32 (betag)
__device__ __half g_hH  [ROWS*Dd];      // rmsnorm(x), fp16 (GEMM A)
__device__ float  g_qpre[ROWS*Dd];
__device__ float  g_kpre[ROWS*Dd];
__device__ float  g_vpre[ROWS*Dd];
__device__ float  g_q   [ROWS*Dd];
__device__ float  g_k   [ROWS*Dd];
__device__ float  g_v   [ROWS*Dd];
__device__ float  g_beta[ROWS*Hh];
__device__ float  g_g   [ROWS*Hh];
__device__ float  g_o   [ROWS*Dd];      // scan output fp32
__device__ __half g_oH  [ROWS*Dd];      // o-rmsnormed fp16 (GEMM A)
__device__ float  g_h2  [ROWS*Dd];
__device__ __half g_h3H [ROWS*Dd];      // mlp rmsnorm fp16 (GEMM A)
__device__ float  g_gy  [ROWS*2*II];
__device__ __half g_actH[ROWS*II];      // swiglu fp16 (GEMM A)
// fp16 weights
__device__ __half g_WqH[Dd*Dd];
__device__ __half g_WkH[Dd*Dd];
__device__ __half g_WvH[Dd*Dd];
__device__ __half g_WoH[Dd*Dd];
__device__ __half g_WgH[Dd*2*II];
__device__ __half g_WdH[II*Dd];

// ---------------------------------------------------------------------------
// Weight f32 -> f16 conversion: one launch, grid.z selects matrix.
// ---------------------------------------------------------------------------
__global__ void wcvt_kernel(const float* __restrict__ w0, __half* o0, int n0,
                            const float* __restrict__ w1, __half* o1, int n1,
                            const float* __restrict__ w2, __half* o2, int n2,
                            const float* __restrict__ w3, __half* o3, int n3,
                            const float* __restrict__ w4, __half* o4, int n4,
                            const float* __restrict__ w5, __half* o5, int n5) {
    const float* w; __half* o; int n;
    switch (blockIdx.y) {
        case 0: w = w0; o = o0; n = n0; break;
        case 1: w = w1; o = o1; n = n1; break;
        case 2: w = w2; o = o2; n = n2; break;
        case 3: w = w3; o = o3; n = n3; break;
        case 4: w = w4; o = o4; n = n4; break;
        default: w = w5; o = o5; n = n5; break;
    }
    int i = (blockIdx.x * blockDim.x + threadIdx.x) * 2;   // 2 elems/thread
    if (i < n) {
        float2 v = *(const float2*)(w + i);
        *(__half2*)(o + i) = __floats2half2_rn(v.x, v.y);
    }
}

// ---------------------------------------------------------------------------
// RMSNorm over D=1024; writes optional fp32 and optional fp16 outputs.
// ---------------------------------------------------------------------------
__global__ void rmsnorm_kernel(const float* __restrict__ x, const float* __restrict__ w,
                               float* __restrict__ outF, __half* __restrict__ outH) {
    int row = blockIdx.x;
    const float4* xr = (const float4*)(x + (size_t)row * Dd);
    float4 v = xr[threadIdx.x];
    float ss = v.x*v.x + v.y*v.y + v.z*v.z + v.w*v.w;
    #pragma unroll
    for (int m = 16; m >= 1; m >>= 1) ss += __shfl_xor_sync(0xffffffffu, ss, m);
    __shared__ float wsum[8];
    if ((threadIdx.x & 31) == 0) wsum[threadIdx.x >> 5] = ss;
    __syncthreads();
    float tot = wsum[0]+wsum[1]+wsum[2]+wsum[3]+wsum[4]+wsum[5]+wsum[6]+wsum[7];
    float r = rsqrtf(tot * (1.0f/Dd) + EPSf);
    float4 wv = ((const float4*)w)[threadIdx.x];
    float4 o;
    o.x = v.x*r*wv.x; o.y = v.y*r*wv.y; o.z = v.z*r*wv.z; o.w = v.w*r*wv.w;
    if (outF)
        ((float4*)(outF + (size_t)row * Dd))[threadIdx.x] = o;
    if (outH) {
        __half2 p0 = __floats2half2_rn(o.x, o.y);
        __half2 p1 = __floats2half2_rn(o.z, o.w);
        ((__half2*)(outH + (size_t)row * Dd))[threadIdx.x*2]   = p0;
        ((__half2*)(outH + (size_t)row * Dd))[threadIdx.x*2+1] = p1;
    }
}

// ---------------------------------------------------------------------------
// FP16 tensor-core GEMM: C[M,N](f32) = A[M,K](f16) @ B[K,N](f16) (+addsrc f32)
// BM=128 BN=128 BK=32, 256 threads, warp tile 64x32, mma.m16n8k16,
// ldmatrix (A: x4, B: x2.trans), double-buffered smem. (R11-proven layout.)
// ---------------------------------------------------------------------------
#define GBM 128
#define GBN 128
#define GBK 32
#define A_ROW_H 40
#define B_ROW_H 136

__device__ __forceinline__ void mma_f16(float& c0, float& c1, float& c2, float& c3,
                                        uint32_t a0, uint32_t a1, uint32_t a2, uint32_t a3,
                                        uint32_t b0, uint32_t b1) {
    asm volatile(
        "mma.sync.aligned.m16n8k16.row.col.f32.f16.f16.f32 "
        "{%0,%1,%2,%3}, {%4,%5,%6,%7}, {%8,%9}, {%0,%1,%2,%3};"
        : "+f"(c0), "+f"(c1), "+f"(c2), "+f"(c3)
        : "r"(a0), "r"(a1), "r"(a2), "r"(a3), "r"(b0), "r"(b1));
}

__device__ __forceinline__ void ldsm_x4(uint32_t* r, uint32_t addr) {
    asm volatile("ldmatrix.sync.aligned.m8n8.x4.shared.b16 {%0,%1,%2,%3}, [%4];"
                 : "=r"(r[0]), "=r"(r[1]), "=r"(r[2]), "=r"(r[3]) : "r"(addr));
}
__device__ __forceinline__ void ldsm_x2t(uint32_t* r, uint32_t addr) {
    asm volatile("ldmatrix.sync.aligned.m8n8.x2.trans.shared.b16 {%0,%1}, [%2];"
                 : "=r"(r[0]), "=r"(r[1]) : "r"(addr));
}

__device__ __forceinline__ void mma_gemm_body(
    const __half* __restrict__ A, const __half* __restrict__ B,
    const float* __restrict__ addsrc, float* __restrict__ C,
    int N, int Kd, int bm, int bn) {
    __shared__ __align__(16) __half As[2][128*A_ROW_H];
    __shared__ __align__(16) __half Bs[2][32*B_ROW_H];

    int tid = threadIdx.x;
    int lane = tid & 31;
    int w    = tid >> 5;
    int lq = lane >> 2;
    int lr = lane & 3;
    int wm = w >> 2;
    int wn = w & 3;

    // A staging: thread -> (row, 16-half group); 2x uint4 (16B) each
    int a_row = tid >> 1;
    int a_h16 = (tid & 1) * 16;
    const __half* Ag = A + (size_t)(bm + a_row) * Kd + a_h16;
    int a_soff = a_row*A_ROW_H + a_h16;

    // B staging: thread -> (k row, 16-half group)
    int b_k  = tid >> 3;
    int b_n0 = (tid & 7) * 16;
    const __half* Bg = B + (size_t)b_k * N + bn + b_n0;
    int b_soff = b_k*B_ROW_H + b_n0;

    float acc[4][4][4];
    #pragma unroll
    for (int mi = 0; mi < 4; mi++)
        #pragma unroll
        for (int ni = 0; ni < 4; ni++)
            #pragma unroll
            for (int r = 0; r < 4; r++) acc[mi][ni][r] = 0.0f;

    int nch = Kd / GBK;

    uint4 arh[2], brh[2];
    arh[0] = *(const uint4*)(Ag);
    arh[1] = *(const uint4*)(Ag + 8);
    brh[0] = *(const uint4*)(Bg);
    brh[1] = *(const uint4*)(Bg + 8);

    *(uint4*)&As[0][a_soff]     = arh[0];
    *(uint4*)&As[0][a_soff + 8] = arh[1];
    *(uint4*)&Bs[0][b_soff]     = brh[0];
    *(uint4*)&Bs[0][b_soff + 8] = brh[1];
    __syncthreads();

    for (int ch = 0; ch < nch; ch++) {
        int s = ch & 1;
        if (ch + 1 < nch) {
            const __half* Agn = Ag + (ch + 1) * GBK;
            const __half* Bgn = Bg + (size_t)(ch + 1) * GBK * N;
            arh[0] = *(const uint4*)(Agn);
            arh[1] = *(const uint4*)(Agn + 8);
            brh[0] = *(const uint4*)(Bgn);
            brh[1] = *(const uint4*)(Bgn + 8);
        }

        #pragma unroll
        for (int ksi = 0; ksi < 2; ksi++) {
            uint32_t af[4][4];
            #pragma unroll
            for (int mi = 0; mi < 4; mi++) {
                int r = wm*64 + mi*16 + (lane & 15);
                uint32_t ad = (uint32_t)__cvta_generic_to_shared(
                    &As[s][r*A_ROW_H + ksi*16 + (lane >> 4)*8]);
                ldsm_x4(af[mi], ad);
            }
            uint32_t bf[4][2];
            #pragma unroll
            for (int ni = 0; ni < 4; ni++) {
                int kr = ksi*16 + (lane & 15);
                uint32_t ad = (uint32_t)__cvta_generic_to_shared(
                    &Bs[s][kr*B_ROW_H + wn*32 + ni*8]);
                ldsm_x2t(bf[ni], ad);
            }
            #pragma unroll
            for (int mi = 0; mi < 4; mi++)
                #pragma unroll
                for (int ni = 0; ni < 4; ni++)
                    mma_f16(acc[mi][ni][0], acc[mi][ni][1], acc[mi][ni][2], acc[mi][ni][3],
                            af[mi][0], af[mi][1], af[mi][2], af[mi][3],
                            bf[ni][0], bf[ni][1]);
        }

        if (ch + 1 < nch) {
            int s1 = s ^ 1;
            *(uint4*)&As[s1][a_soff]     = arh[0];
            *(uint4*)&As[s1][a_soff + 8] = arh[1];
            *(uint4*)&Bs[s1][b_soff]     = brh[0];
            *(uint4*)&Bs[s1][b_soff + 8] = brh[1];
            __syncthreads();
        }
    }

    #pragma unroll
    for (int mi = 0; mi < 4; mi++) {
        int r0 = bm + wm*64 + mi*16 + lq;
        #pragma unroll
        for (int ni = 0; ni < 4; ni++) {
            int col = bn + wn*32 + ni*8 + 2*lr;
            float2 v0 = make_float2(acc[mi][ni][0], acc[mi][ni][1]);
            float2 v1 = make_float2(acc[mi][ni][2], acc[mi][ni][3]);
            if (addsrc) {
                float2 s0 = *(const float2*)(addsrc + (size_t)r0 * N + col);
                float2 s1 = *(const float2*)(addsrc + (size_t)(r0+8) * N + col);
                v0.x += s0.x; v0.y += s0.y; v1.x += s1.x; v1.y += s1.y;
            }
            *(float2*)(C + (size_t)r0 * N + col) = v0;
            *(float2*)(C + (size_t)(r0+8) * N + col) = v1;
        }
    }
}

__global__ __launch_bounds__(256, 2) void mma_gemm_kernel(
    const __half* __restrict__ A, const __half* __restrict__ B,
    const float* __restrict__ addsrc, float* __restrict__ C,
    int N, int Kd) {
    mma_gemm_body(A, B, addsrc, C, N, Kd, blockIdx.y * GBM, blockIdx.x * GBN);
}

__global__ __launch_bounds__(256, 2) void mma_gemm_qkv_kernel(
    const __half* __restrict__ A,
    const __half* __restrict__ B0, const __half* __restrict__ B1, const __half* __restrict__ B2,
    float* __restrict__ C0, float* __restrict__ C1, float* __restrict__ C2,
    int N, int Kd) {
    const __half* B = (blockIdx.z == 0) ? B0 : ((blockIdx.z == 1) ? B1 : B2);
    float*        C = (blockIdx.z == 0) ? C0 : ((blockIdx.z == 1) ? C1 : C2);
    mma_gemm_body(A, B, nullptr, C, N, Kd, blockIdx.y * GBM, blockIdx.x * GBN);
}

// ---------------------------------------------------------------------------
// Fused causal depthwise conv1d (K=4) + SiLU + optional per-head L2 norm.
// ---------------------------------------------------------------------------
__global__ void conv_fused3_kernel(
    const float* __restrict__ xq, const float* __restrict__ wq, float* __restrict__ oq,
    const float* __restrict__ xk, const float* __restrict__ wk, float* __restrict__ ok,
    const float* __restrict__ xv, const float* __restrict__ wv, float* __restrict__ ov) {
    int which = blockIdx.y;
    const float* xin = (which == 0) ? xq : ((which == 1) ? xk : xv);
    const float* w   = (which == 0) ? wq : ((which == 1) ? wk : wv);
    float* out       = (which == 0) ? oq : ((which == 1) ? ok : ov);
    float scale = (which == 0) ? 0.125f : 1.0f;
    int do_l2   = (which != 2);

    int row = blockIdx.x;
    int t = row & (Tt - 1);
    int c4 = threadIdx.x * 4;
    size_t base = (size_t)row * Dd + c4;

    float4 x0 = *(const float4*)(xin + base);
    float4 x1 = (t >= 1) ? *(const float4*)(xin + base - Dd)   : make_float4(0,0,0,0);
    float4 x2 = (t >= 2) ? *(const float4*)(xin + base - 2*Dd) : make_float4(0,0,0,0);
    float4 x3 = (t >= 3) ? *(const float4*)(xin + base - 3*Dd) : make_float4(0,0,0,0);

    float y[4];
    #pragma unroll
    for (int j = 0; j < 4; j++) {
        float4 w4 = ((const float4*)w)[c4 + j];
        float a = (&x0.x)[j]*w4.w + (&x1.x)[j]*w4.z + (&x2.x)[j]*w4.y + (&x3.x)[j]*w4.x;
        y[j] = a / (1.0f + expf(-a));
    }

    if (do_l2) {
        float ss = y[0]*y[0] + y[1]*y[1] + y[2]*y[2] + y[3]*y[3];
        #pragma unroll
        for (int m = 8; m >= 1; m >>= 1) ss += __shfl_xor_sync(0xffffffffu, ss, m);
        float r = rsqrtf(ss + EPSf) * scale;
        #pragma unroll
        for (int j = 0; j < 4; j++) y[j] *= r;
    }
    *(float4*)(out + base) = make_float4(y[0], y[1], y[2], y[3]);
}

// ---------------------------------------------------------------------------
// Per-(b,t,h) RMSNorm over DV=64; reads fp32 o, writes fp16 oH.
// ---------------------------------------------------------------------------
__global__ void o_rmsnorm_kernel(const float* __restrict__ o, const float* __restrict__ w,
                                 __half* __restrict__ oH) {
    int gidx = blockIdx.x * 8 + (threadIdx.x >> 5);
    int lane = threadIdx.x & 31;
    size_t base = (size_t)gidx * 64;
    float a = o[base + lane], b = o[base + 32 + lane];
    float ss = a*a + b*b;
    #pragma unroll
    for (int m = 16; m >= 1; m >>= 1) ss += __shfl_xor_sync(0xffffffffu, ss, m);
    float r = rsqrtf(ss * (1.0f/64.0f) + EPSf);
    oH[base + lane]      = __float2half_rn(a * r * w[lane]);
    oH[base + 32 + lane] = __float2half_rn(b * r * w[lane + 32]);
}

// ---------------------------------------------------------------------------
// beta / g projections (R10 winner)
// ---------------------------------------------------------------------------
#define BETAG_BLOCKS 128
#define BETAG_RPB 32
#define BETAG_PASS 16
#define BETAG_SMEM_FLTS (2*Dd*Hh + BETAG_PASS*Dd)
#define BETAG_SMEM_BYTES (BETAG_SMEM_FLTS*4)

__global__ __launch_bounds__(256) void betag_kernel(
    const float* __restrict__ h,
    const float* __restrict__ Wb, const float* __restrict__ Wa,
    const float* __restrict__ dt_bias, const float* __restrict__ A_log,
    float* __restrict__ beta, float* __restrict__ g) {
    extern __shared__ float bsm[];
    float* wbs = bsm;
    float* was = bsm + Dd*Hh;
    float* hst = bsm + 2*Dd*Hh;

    int tid = threadIdx.x;
    int hh  = tid & 15;
    int grp = tid >> 4;
    int row0 = blockIdx.x * BETAG_RPB;

    for (int i = tid; i < 8192; i += 256) {
        float4 vb = ((const float4*)Wb)[i & 4095];
        if (i < 4096) ((float4*)wbs)[i] = vb;
        else          ((float4*)was)[i - 4096] = ((const float4*)Wa)[i - 4096];
    }

    for (int p = 0; p < 2; p++) {
        int prow0 = row0 + p * BETAG_PASS;
        __syncthreads();
        for (int i = tid; i < 4096; i += 256)
            ((float4*)hst)[i] = ((const float4*)(h + (size_t)prow0 * Dd))[i];
        __syncthreads();

        float sb[BETAG_PASS], sa[BETAG_PASS];
        #pragma unroll
        for (int r = 0; r < BETAG_PASS; r++) { sb[r] = 0.0f; sa[r] = 0.0f; }

        #pragma unroll 4
        for (int j = 0; j < 64; j++) {
            int d = j*16 + grp;
            float wb = wbs[d*Hh + hh];
            float wa = was[d*Hh + hh];
            #pragma unroll
            for (int r = 0; r < BETAG_PASS; r++) {
                float hv = hst[r*Dd + d];
                sb[r] += hv * wb;
                sa[r] += hv * wa;
            }
        }
        __syncthreads();

        #pragma unroll
        for (int r = 0; r < BETAG_PASS; r++) {
            hst[(r<<9) + (grp<<4) + hh]       = sb[r];
            hst[(r<<9) + 256 + (grp<<4) + hh] = sa[r];
        }
        __syncthreads();

        #pragma unroll
        for (int u = 0; u < 2; u++) {
            int idx = tid + u*256;
            int r2    = idx >> 5;
            int which = (idx >> 4) & 1;
            int hh2   = idx & 15;
            const float* rp = hst + (r2<<9) + which*256 + hh2;
            float s = 0.0f;
            #pragma unroll
            for (int gg2 = 0; gg2 < 16; gg2++) s += rp[gg2*16];
            int row = prow0 + r2;
            if (which == 0) {
                beta[row*Hh + hh2] = 2.0f / (1.0f + expf(-s));
            } else {
                float xg = s + dt_bias[hh2];
                float sp = (xg > 15.0f) ? xg : log1pf(expf(xg));
                g[row*Hh + hh2] = -expf(A_log[hh2]) * sp;
            }
        }
    }
}

// ---------------------------------------------------------------------------
// Gated delta-rule scan (R11 winner: 16 rows/thread, 4-way chain split).
// ---------------------------------------------------------------------------
__device__ __forceinline__ float scan_load(const float* __restrict__ q,
                                           const float* __restrict__ k,
                                           const float* __restrict__ v,
                                           const float* __restrict__ beta,
                                           const float* __restrict__ g,
                                           int b, int h, int t, int tid) {
    size_t off = ((size_t)(b*Tt + t)) * 1024 + h * 64;
    if (tid < 64)  return k[off + tid];
    if (tid < 128) return q[off + tid - 64];
    if (tid < 192) return v[off + tid - 128];
    if (tid == 192) return beta[(size_t)(b*Tt + t)*Hh + h];
    return g[(size_t)(b*Tt + t)*Hh + h];
}

__global__ __launch_bounds__(256) void scan_kernel(
    const float* __restrict__ q, const float* __restrict__ k, const float* __restrict__ v,
    const float* __restrict__ beta, const float* __restrict__ g,
    float* __restrict__ o, float* __restrict__ state_out) {
    int h = blockIdx.x, b = blockIdx.y;
    int tid = threadIdx.x;
    int c   = tid >> 2;
    int sub = tid & 3;

    __shared__ __align__(16) float sh[2][200];

    float S[16];
    #pragma unroll
    for (int r = 0; r < 16; r++) S[r] = 0.0f;

    float rv = (tid < 194) ? scan_load(q, k, v, beta, g, b, h, 0, tid) : 0.0f;

    for (int t = 0; t < Tt; t++) {
        float* buf = sh[t & 1];
        if (tid < 194) buf[tid] = rv;
        __syncthreads();
        if (t + 1 < Tt && tid < 194)
            rv = scan_load(q, k, v, beta, g, b, h, t + 1, tid);

        float eg = expf(buf[193]);
        float bt = buf[192];

        const float4* kp4 = (const float4*)(buf + sub*16);
        const float4* qp4 = (const float4*)(buf + 64 + sub*16);
        float kr[16], qr[16];
        #pragma unroll
        for (int rr = 0; rr < 4; rr++) {
            float4 kv4 = kp4[rr];
            kr[rr*4+0] = kv4.x; kr[rr*4+1] = kv4.y; kr[rr*4+2] = kv4.z; kr[rr*4+3] = kv4.w;
            float4 qv4 = qp4[rr];
            qr[rr*4+0] = qv4.x; qr[rr*4+1] = qv4.y; qr[rr*4+2] = qv4.z; qr[rr*4+3] = qv4.w;
        }

        float k0 = 0.0f, k1 = 0.0f, k2 = 0.0f, k3 = 0.0f;
        #pragma unroll
        for (int r4 = 0; r4 < 4; r4++) {
            S[4*r4+0] *= eg; k0 += kr[4*r4+0] * S[4*r4+0];
            S[4*r4+1] *= eg; k1 += kr[4*r4+1] * S[4*r4+1];
            S[4*r4+2] *= eg; k2 += kr[4*r4+2] * S[4*r4+2];
            S[4*r4+3] *= eg; k3 += kr[4*r4+3] * S[4*r4+3];
        }
        float kvp = (k0 + k1) + (k2 + k3);
        kvp += __shfl_xor_sync(0xffffffffu, kvp, 1);
        kvp += __shfl_xor_sync(0xffffffffu, kvp, 2);

        float delta = (buf[128 + c] - kvp) * bt;

        float o0 = 0.0f, o1 = 0.0f, o2 = 0.0f, o3 = 0.0f;
        #pragma unroll
        for (int r4 = 0; r4 < 4; r4++) {
            S[4*r4+0] += kr[4*r4+0] * delta; o0 += qr[4*r4+0] * S[4*r4+0];
            S[4*r4+1] += kr[4*r4+1] * delta; o1 += qr[4*r4+1] * S[4*r4+1];
            S[4*r4+2] += kr[4*r4+2] * delta; o2 += qr[4*r4+2] * S[4*r4+2];
            S[4*r4+3] += kr[4*r4+3] * delta; o3 += qr[4*r4+3] * S[4*r4+3];
        }
        float op = (o0 + o1) + (o2 + o3);
        op += __shfl_xor_sync(0xffffffffu, op, 1);
        op += __shfl_xor_sync(0xffffffffu, op, 2);
        if (sub == 0)
            o[((size_t)(b*Tt + t)*Hh + h) * DV + c] = op;
    }

    #pragma unroll
    for (int r = 0; r < 16; r++)
        state_out[((size_t)(b*Hh + h)*DK + sub*16 + r) * DV + c] = S[r];
}

// ---------------------------------------------------------------------------
// SwiGLU: actH = f16(silu(gy[:, :I]) * gy[:, I:]); 2 elems/thread
// ---------------------------------------------------------------------------
__global__ void swiglu_kernel(const float* __restrict__ gy, __half* __restrict__ actH) {
    int idx2 = blockIdx.x * blockDim.x + threadIdx.x;   // over ROWS*II/2
    int row = idx2 / (II/2);
    int i   = (idx2 - row * (II/2)) * 2;
    float2 gate = *(const float2*)(gy + (size_t)row * (2*II) + i);
    float2 y    = *(const float2*)(gy + (size_t)row * (2*II) + II + i);
    float a0 = gate.x / (1.0f + expf(-gate.x)) * y.x;
    float a1 = gate.y / (1.0f + expf(-gate.y)) * y.y;
    *(__half2*)(actH + (size_t)row * II + i) = __floats2half2_rn(a0, a1);
}

// ---------------------------------------------------------------------------
// launch
// ---------------------------------------------------------------------------
extern "C" void kernel_launch(void* const* d_in, const int* in_sizes, int n_in,
                              void* d_out, int out_size) {
    const float* x           = (const float*)d_in[0];
    const float* attn_norm_w = (const float*)d_in[1];
    const float* Wq          = (const float*)d_in[2];
    const float* Wk          = (const float*)d_in[3];
    const float* Wv          = (const float*)d_in[4];
    const float* cq          = (const float*)d_in[5];
    const float* ck          = (const float*)d_in[6];
    const float* cv          = (const float*)d_in[7];
    const float* Wb          = (const float*)d_in[8];
    const float* Wa          = (const float*)d_in[9];
    const float* dt_bias     = (const float*)d_in[10];
    const float* A_log       = (const float*)d_in[11];
    const float* o_norm_w    = (const float*)d_in[12];
    const float* Wo          = (const float*)d_in[13];
    const float* mlp_norm_w  = (const float*)d_in[14];
    const float* Wg          = (const float*)d_in[15];
    const float* Wd          = (const float*)d_in[16];
    float* out = (float*)d_out;

    float *h, *qpre, *kpre, *vpre, *q, *k, *v, *beta, *gg, *o, *h2, *gy;
    __half *hH, *oH, *h3H, *actH, *WqH, *WkH, *WvH, *WoH, *WgH, *WdH;
    cudaGetSymbolAddress((void**)&h,    g_h);
    cudaGetSymbolAddress((void**)&hH,   g_hH);
    cudaGetSymbolAddress((void**)&qpre, g_qpre);
    cudaGetSymbolAddress((void**)&kpre, g_kpre);
    cudaGetSymbolAddress((void**)&vpre, g_vpre);
    cudaGetSymbolAddress((void**)&q,    g_q);
    cudaGetSymbolAddress((void**)&k,    g_k);
    cudaGetSymbolAddress((void**)&v,    g_v);
    cudaGetSymbolAddress((void**)&beta, g_beta);
    cudaGetSymbolAddress((void**)&gg,   g_g);
    cudaGetSymbolAddress((void**)&o,    g_o);
    cudaGetSymbolAddress((void**)&oH,   g_oH);
    cudaGetSymbolAddress((void**)&h2,   g_h2);
    cudaGetSymbolAddress((void**)&h3H,  g_h3H);
    cudaGetSymbolAddress((void**)&gy,   g_gy);
    cudaGetSymbolAddress((void**)&actH, g_actH);
    cudaGetSymbolAddress((void**)&WqH,  g_WqH);
    cudaGetSymbolAddress((void**)&WkH,  g_WkH);
    cudaGetSymbolAddress((void**)&WvH,  g_WvH);
    cudaGetSymbolAddress((void**)&WoH,  g_WoH);
    cudaGetSymbolAddress((void**)&WgH,  g_WgH);
    cudaGetSymbolAddress((void**)&WdH,  g_WdH);

    cudaFuncSetAttribute(betag_kernel,
                         cudaFuncAttributeMaxDynamicSharedMemorySize, BETAG_SMEM_BYTES);

    // 0. weights -> fp16 (one launch; grid sized for the largest matrix)
    {
        int nmax = Dd*2*II;                       // 5.77M elems
        int blocks = (nmax/2 + 255) / 256;
        dim3 gw(blocks, 6);
        wcvt_kernel<<<gw, 256>>>(Wq, WqH, Dd*Dd, Wk, WkH, Dd*Dd, Wv, WvH, Dd*Dd,
                                 Wo, WoH, Dd*Dd, Wg, WgH, Dd*2*II, Wd, WdH, II*Dd);
    }

    // 1. h = rmsnorm(x) -> fp32 (betag) + fp16 (GEMM)
    rmsnorm_kernel<<<ROWS, 256>>>(x, attn_norm_w, h, hH);

    // 2. q/k/v projections
    dim3 gqkv(Dd/GBN, ROWS/GBM, 3);
    mma_gemm_qkv_kernel<<<gqkv, 256>>>(hH, WqH, WkH, WvH, qpre, kpre, vpre, Dd, Dd);

    // 3. conv + silu (+ fused l2norm for q,k)
    conv_fused3_kernel<<<dim3(ROWS, 3), 256>>>(qpre, cq, q, kpre, ck, k, vpre, cv, v);

    // 4. beta / g
    betag_kernel<<<BETAG_BLOCKS, 256, BETAG_SMEM_BYTES>>>(h, Wb, Wa, dt_bias, A_log, beta, gg);

    // 5. delta-rule scan
    scan_kernel<<<dim3(Hh, Bb), 256>>>(q, k, v, beta, gg, o, out + (size_t)ROWS*Dd);

    // 6. per-head output RMSNorm -> fp16
    o_rmsnorm_kernel<<<(ROWS*Hh)/8, 256>>>(o, o_norm_w, oH);

    // 7. attn projection + residual
    dim3 g1024(Dd/GBN, ROWS/GBM);
    mma_gemm_kernel<<<g1024, 256>>>(oH, WoH, x, h2, Dd, Dd);

    // 8. MLP
    rmsnorm_kernel<<<ROWS, 256>>>(h2, mlp_norm_w, nullptr, h3H);
    dim3 gwg((2*II)/GBN, ROWS/GBM);
    mma_gemm_kernel<<<gwg, 256>>>(h3H, WgH, nullptr, gy, 2*II, Dd);
    swiglu_kernel<<<(ROWS*II/2)/256, 256>>>(gy, actH);
    mma_gemm_kernel<<<g1024, 256>>>(actH, WdH, h2, out, Dd, II);
}

// round 15
// speedup vs baseline: 1.7211x; 1.0604x over previous
#include <cuda_runtime.h>
#include <cuda_fp16.h>
#include <math.h>
#include <stdint.h>

// ---------------------------------------------------------------------------
// Problem constants
// ---------------------------------------------------------------------------
#define Bb   4
#define Tt   1024
#define Dd   1024
#define Hh   16
#define DK   64
#define DV   64
#define II   2816
#define EPSf 1e-6f
#define ROWS (Bb*Tt)              // 4096

// ---------------------------------------------------------------------------
// Scratch (static device memory; no allocations allowed)
// ---------------------------------------------------------------------------
__device__ float  g_h   [ROWS*Dd];      // rmsnorm(x), fp32 (betag)
__device__ __half g_hH  [ROWS*Dd];      // rmsnorm(x), fp16 (GEMM A)
__device__ float  g_qpre[ROWS*Dd];
__device__ float  g_kpre[ROWS*Dd];
__device__ float  g_vpre[ROWS*Dd];
__device__ float  g_q   [ROWS*Dd];
__device__ float  g_k   [ROWS*Dd];
__device__ float  g_v   [ROWS*Dd];
__device__ float  g_beta[ROWS*Hh];
__device__ float  g_g   [ROWS*Hh];
__device__ float  g_o   [ROWS*Dd];      // scan output fp32
__device__ __half g_oH  [ROWS*Dd];      // o-rmsnormed fp16 (GEMM A)
__device__ float  g_h2  [ROWS*Dd];
__device__ __half g_h3H [ROWS*Dd];      // mlp rmsnorm fp16 (GEMM A)
__device__ __half g_gyH [ROWS*2*II];    // h3 @ Wg, fp16
__device__ __half g_actH[ROWS*II];      // swiglu fp16 (GEMM A)
// fp16 weights
__device__ __half g_WqH[Dd*Dd];
__device__ __half g_WkH[Dd*Dd];
__device__ __half g_WvH[Dd*Dd];
__device__ __half g_WoH[Dd*Dd];
__device__ __half g_WgH[Dd*2*II];
__device__ __half g_WdH[II*Dd];

// ---------------------------------------------------------------------------
// Weight f32 -> f16 conversion: one launch, grid.y selects matrix.
// ---------------------------------------------------------------------------
__global__ void wcvt_kernel(const float* __restrict__ w0, __half* o0, int n0,
                            const float* __restrict__ w1, __half* o1, int n1,
                            const float* __restrict__ w2, __half* o2, int n2,
                            const float* __restrict__ w3, __half* o3, int n3,
                            const float* __restrict__ w4, __half* o4, int n4,
                            const float* __restrict__ w5, __half* o5, int n5) {
    const float* w; __half* o; int n;
    switch (blockIdx.y) {
        case 0: w = w0; o = o0; n = n0; break;
        case 1: w = w1; o = o1; n = n1; break;
        case 2: w = w2; o = o2; n = n2; break;
        case 3: w = w3; o = o3; n = n3; break;
        case 4: w = w4; o = o4; n = n4; break;
        default: w = w5; o = o5; n = n5; break;
    }
    int i = (blockIdx.x * blockDim.x + threadIdx.x) * 2;
    if (i < n) {
        float2 v = *(const float2*)(w + i);
        *(__half2*)(o + i) = __floats2half2_rn(v.x, v.y);
    }
}

// ---------------------------------------------------------------------------
// RMSNorm over D=1024; writes optional fp32 and optional fp16 outputs.
// ---------------------------------------------------------------------------
__global__ void rmsnorm_kernel(const float* __restrict__ x, const float* __restrict__ w,
                               float* __restrict__ outF, __half* __restrict__ outH) {
    int row = blockIdx.x;
    const float4* xr = (const float4*)(x + (size_t)row * Dd);
    float4 v = xr[threadIdx.x];
    float ss = v.x*v.x + v.y*v.y + v.z*v.z + v.w*v.w;
    #pragma unroll
    for (int m = 16; m >= 1; m >>= 1) ss += __shfl_xor_sync(0xffffffffu, ss, m);
    __shared__ float wsum[8];
    if ((threadIdx.x & 31) == 0) wsum[threadIdx.x >> 5] = ss;
    __syncthreads();
    float tot = wsum[0]+wsum[1]+wsum[2]+wsum[3]+wsum[4]+wsum[5]+wsum[6]+wsum[7];
    float r = rsqrtf(tot * (1.0f/Dd) + EPSf);
    float4 wv = ((const float4*)w)[threadIdx.x];
    float4 o;
    o.x = v.x*r*wv.x; o.y = v.y*r*wv.y; o.z = v.z*r*wv.z; o.w = v.w*r*wv.w;
    if (outF)
        ((float4*)(outF + (size_t)row * Dd))[threadIdx.x] = o;
    if (outH) {
        __half2 p0 = __floats2half2_rn(o.x, o.y);
        __half2 p1 = __floats2half2_rn(o.z, o.w);
        ((__half2*)(outH + (size_t)row * Dd))[threadIdx.x*2]   = p0;
        ((__half2*)(outH + (size_t)row * Dd))[threadIdx.x*2+1] = p1;
    }
}

// ---------------------------------------------------------------------------
// FP16 tensor-core GEMM with 4-stage cp.async pipeline.
// C[M,N] = A[M,K](f16) @ B[K,N](f16) (+addsrc f32), f32 accum.
// BM=128 BN=128 BK=32, 256 threads, warp tile 64x32, mma.m16n8k16,
// ldmatrix (A: x4, B: x2.trans). Dynamic smem, 2 CTAs/SM.
// ---------------------------------------------------------------------------
#define GBM 128
#define GBN 128
#define GBK 32
#define A_ROW_H 40
#define B_ROW_H 136
#define A_ST (128*A_ROW_H)          // 5120 halfs / stage
#define B_ST (32*B_ROW_H)           // 4352 halfs / stage
#define NSTAGE 4
#define GEMM_DYN_BYTES ((NSTAGE*(A_ST + B_ST))*2)   // 75776 B

__device__ __forceinline__ void mma_f16(float& c0, float& c1, float& c2, float& c3,
                                        uint32_t a0, uint32_t a1, uint32_t a2, uint32_t a3,
                                        uint32_t b0, uint32_t b1) {
    asm volatile(
        "mma.sync.aligned.m16n8k16.row.col.f32.f16.f16.f32 "
        "{%0,%1,%2,%3}, {%4,%5,%6,%7}, {%8,%9}, {%0,%1,%2,%3};"
        : "+f"(c0), "+f"(c1), "+f"(c2), "+f"(c3)
        : "r"(a0), "r"(a1), "r"(a2), "r"(a3), "r"(b0), "r"(b1));
}

__device__ __forceinline__ void ldsm_x4(uint32_t* r, uint32_t addr) {
    asm volatile("ldmatrix.sync.aligned.m8n8.x4.shared.b16 {%0,%1,%2,%3}, [%4];"
                 : "=r"(r[0]), "=r"(r[1]), "=r"(r[2]), "=r"(r[3]) : "r"(addr));
}
__device__ __forceinline__ void ldsm_x2t(uint32_t* r, uint32_t addr) {
    asm volatile("ldmatrix.sync.aligned.m8n8.x2.trans.shared.b16 {%0,%1}, [%2];"
                 : "=r"(r[0]), "=r"(r[1]) : "r"(addr));
}

__device__ __forceinline__ void cpa16(uint32_t saddr, const void* g) {
    asm volatile("cp.async.cg.shared.global [%0], [%1], 16;" :: "r"(saddr), "l"(g));
}
#define CP_COMMIT() asm volatile("cp.async.commit_group;" ::: "memory")
#define CP_WAIT2()  asm volatile("cp.async.wait_group 2;" ::: "memory")

template<int OUT_HALF>
__device__ __forceinline__ void mma_gemm_body(
    const __half* __restrict__ A, const __half* __restrict__ B,
    const float* __restrict__ addsrc, void* __restrict__ Cv,
    int N, int Kd, int bm, int bn) {
    extern __shared__ __align__(16) __half gsm[];
    __half* Asm = gsm;                    // [NSTAGE][A_ST]
    __half* Bsm = gsm + NSTAGE*A_ST;      // [NSTAGE][B_ST]

    int tid = threadIdx.x;
    int lane = tid & 31;
    int w    = tid >> 5;
    int lq = lane >> 2;
    int lr = lane & 3;
    int wm = w >> 2;
    int wn = w & 3;

    // A staging: thread -> (row, 16-half group)
    int a_row = tid >> 1;
    int a_h16 = (tid & 1) * 16;
    const __half* Ag = A + (size_t)(bm + a_row) * Kd + a_h16;
    int a_soff = a_row*A_ROW_H + a_h16;

    // B staging: thread -> (k row, 16-half group)
    int b_k  = tid >> 3;
    int b_n0 = (tid & 7) * 16;
    const __half* Bg = B + (size_t)b_k * N + bn + b_n0;
    int b_soff = b_k*B_ROW_H + b_n0;

    int nch = Kd / GBK;

    // issue one stage of cp.async (4x16B per thread)
    auto issue_stage = [&](int ch) {
        int s = ch & (NSTAGE-1);
        const __half* Agn = Ag + ch * GBK;
        const __half* Bgn = Bg + (size_t)ch * GBK * N;
        uint32_t as = (uint32_t)__cvta_generic_to_shared(&Asm[s*A_ST + a_soff]);
        cpa16(as,      Agn);
        cpa16(as + 16, Agn + 8);
        uint32_t bs = (uint32_t)__cvta_generic_to_shared(&Bsm[s*B_ST + b_soff]);
        cpa16(bs,      Bgn);
        cpa16(bs + 16, Bgn + 8);
    };

    float acc[4][4][4];
    #pragma unroll
    for (int mi = 0; mi < 4; mi++)
        #pragma unroll
        for (int ni = 0; ni < 4; ni++)
            #pragma unroll
            for (int r = 0; r < 4; r++) acc[mi][ni][r] = 0.0f;

    // prologue: stages 0..2
    issue_stage(0); CP_COMMIT();
    issue_stage(1); CP_COMMIT();
    issue_stage(2); CP_COMMIT();

    for (int ch = 0; ch < nch; ch++) {
        int s = ch & (NSTAGE-1);
        CP_WAIT2();
        __syncthreads();

        const __half* As = Asm + s*A_ST;
        const __half* Bs = Bsm + s*B_ST;
        #pragma unroll
        for (int ksi = 0; ksi < 2; ksi++) {
            uint32_t af[4][4];
            #pragma unroll
            for (int mi = 0; mi < 4; mi++) {
                int r = wm*64 + mi*16 + (lane & 15);
                uint32_t ad = (uint32_t)__cvta_generic_to_shared(
                    &As[r*A_ROW_H + ksi*16 + (lane >> 4)*8]);
                ldsm_x4(af[mi], ad);
            }
            uint32_t bf[4][2];
            #pragma unroll
            for (int ni = 0; ni < 4; ni++) {
                int kr = ksi*16 + (lane & 15);
                uint32_t ad = (uint32_t)__cvta_generic_to_shared(
                    &Bs[kr*B_ROW_H + wn*32 + ni*8]);
                ldsm_x2t(bf[ni], ad);
            }
            #pragma unroll
            for (int mi = 0; mi < 4; mi++)
                #pragma unroll
                for (int ni = 0; ni < 4; ni++)
                    mma_f16(acc[mi][ni][0], acc[mi][ni][1], acc[mi][ni][2], acc[mi][ni][3],
                            af[mi][0], af[mi][1], af[mi][2], af[mi][3],
                            bf[ni][0], bf[ni][1]);
        }
        __syncthreads();
        if (ch + NSTAGE - 1 < nch) issue_stage(ch + NSTAGE - 1);
        CP_COMMIT();                 // empty commit in tail keeps group count uniform
    }

    // epilogue
    #pragma unroll
    for (int mi = 0; mi < 4; mi++) {
        int r0 = bm + wm*64 + mi*16 + lq;
        #pragma unroll
        for (int ni = 0; ni < 4; ni++) {
            int col = bn + wn*32 + ni*8 + 2*lr;
            float2 v0 = make_float2(acc[mi][ni][0], acc[mi][ni][1]);
            float2 v1 = make_float2(acc[mi][ni][2], acc[mi][ni][3]);
            if (OUT_HALF) {
                __half* C = (__half*)Cv;
                *(__half2*)(C + (size_t)r0 * N + col)     = __floats2half2_rn(v0.x, v0.y);
                *(__half2*)(C + (size_t)(r0+8) * N + col) = __floats2half2_rn(v1.x, v1.y);
            } else {
                float* C = (float*)Cv;
                if (addsrc) {
                    float2 s0 = *(const float2*)(addsrc + (size_t)r0 * N + col);
                    float2 s1 = *(const float2*)(addsrc + (size_t)(r0+8) * N + col);
                    v0.x += s0.x; v0.y += s0.y; v1.x += s1.x; v1.y += s1.y;
                }
                *(float2*)(C + (size_t)r0 * N + col) = v0;
                *(float2*)(C + (size_t)(r0+8) * N + col) = v1;
            }
        }
    }
}

__global__ __launch_bounds__(256, 2) void mma_gemm_kernel(
    const __half* __restrict__ A, const __half* __restrict__ B,
    const float* __restrict__ addsrc, float* __restrict__ C,
    int N, int Kd) {
    mma_gemm_body<0>(A, B, addsrc, C, N, Kd, blockIdx.y * GBM, blockIdx.x * GBN);
}

__global__ __launch_bounds__(256, 2) void mma_gemm_qkv_kernel(
    const __half* __restrict__ A,
    const __half* __restrict__ B0, const __half* __restrict__ B1, const __half* __restrict__ B2,
    float* __restrict__ C0, float* __restrict__ C1, float* __restrict__ C2,
    int N, int Kd) {
    const __half* B = (blockIdx.z == 0) ? B0 : ((blockIdx.z == 1) ? B1 : B2);
    float*        C = (blockIdx.z == 0) ? C0 : ((blockIdx.z == 1) ? C1 : C2);
    mma_gemm_body<0>(A, B, nullptr, C, N, Kd, blockIdx.y * GBM, blockIdx.x * GBN);
}

__global__ __launch_bounds__(256, 2) void mma_gemm_h_kernel(
    const __half* __restrict__ A, const __half* __restrict__ B,
    __half* __restrict__ C, int N, int Kd) {
    mma_gemm_body<1>(A, B, nullptr, C, N, Kd, blockIdx.y * GBM, blockIdx.x * GBN);
}

// ---------------------------------------------------------------------------
// Fused causal depthwise conv1d (K=4) + SiLU + optional per-head L2 norm.
// ---------------------------------------------------------------------------
__global__ void conv_fused3_kernel(
    const float* __restrict__ xq, const float* __restrict__ wq, float* __restrict__ oq,
    const float* __restrict__ xk, const float* __restrict__ wk, float* __restrict__ ok,
    const float* __restrict__ xv, const float* __restrict__ wv, float* __restrict__ ov) {
    int which = blockIdx.y;
    const float* xin = (which == 0) ? xq : ((which == 1) ? xk : xv);
    const float* w   = (which == 0) ? wq : ((which == 1) ? wk : wv);
    float* out       = (which == 0) ? oq : ((which == 1) ? ok : ov);
    float scale = (which == 0) ? 0.125f : 1.0f;
    int do_l2   = (which != 2);

    int row = blockIdx.x;
    int t = row & (Tt - 1);
    int c4 = threadIdx.x * 4;
    size_t base = (size_t)row * Dd + c4;

    float4 x0 = *(const float4*)(xin + base);
    float4 x1 = (t >= 1) ? *(const float4*)(xin + base - Dd)   : make_float4(0,0,0,0);
    float4 x2 = (t >= 2) ? *(const float4*)(xin + base - 2*Dd) : make_float4(0,0,0,0);
    float4 x3 = (t >= 3) ? *(const float4*)(xin + base - 3*Dd) : make_float4(0,0,0,0);

    float y[4];
    #pragma unroll
    for (int j = 0; j < 4; j++) {
        float4 w4 = ((const float4*)w)[c4 + j];
        float a = (&x0.x)[j]*w4.w + (&x1.x)[j]*w4.z + (&x2.x)[j]*w4.y + (&x3.x)[j]*w4.x;
        y[j] = a / (1.0f + expf(-a));
    }

    if (do_l2) {
        float ss = y[0]*y[0] + y[1]*y[1] + y[2]*y[2] + y[3]*y[3];
        #pragma unroll
        for (int m = 8; m >= 1; m >>= 1) ss += __shfl_xor_sync(0xffffffffu, ss, m);
        float r = rsqrtf(ss + EPSf) * scale;
        #pragma unroll
        for (int j = 0; j < 4; j++) y[j] *= r;
    }
    *(float4*)(out + base) = make_float4(y[0], y[1], y[2], y[3]);
}

// ---------------------------------------------------------------------------
// Per-(b,t,h) RMSNorm over DV=64; reads fp32 o, writes fp16 oH.
// ---------------------------------------------------------------------------
__global__ void o_rmsnorm_kernel(const float* __restrict__ o, const float* __restrict__ w,
                                 __half* __restrict__ oH) {
    int gidx = blockIdx.x * 8 + (threadIdx.x >> 5);
    int lane = threadIdx.x & 31;
    size_t base = (size_t)gidx * 64;
    float a = o[base + lane], b = o[base + 32 + lane];
    float ss = a*a + b*b;
    #pragma unroll
    for (int m = 16; m >= 1; m >>= 1) ss += __shfl_xor_sync(0xffffffffu, ss, m);
    float r = rsqrtf(ss * (1.0f/64.0f) + EPSf);
    oH[base + lane]      = __float2half_rn(a * r * w[lane]);
    oH[base + 32 + lane] = __float2half_rn(b * r * w[lane + 32]);
}

// ---------------------------------------------------------------------------
// beta / g projections (R10 winner)
// ---------------------------------------------------------------------------
#define BETAG_BLOCKS 128
#define BETAG_RPB 32
#define BETAG_PASS 16
#define BETAG_SMEM_FLTS (2*Dd*Hh + BETAG_PASS*Dd)
#define BETAG_SMEM_BYTES (BETAG_SMEM_FLTS*4)

__global__ __launch_bounds__(256) void betag_kernel(
    const float* __restrict__ h,
    const float* __restrict__ Wb, const float* __restrict__ Wa,
    const float* __restrict__ dt_bias, const float* __restrict__ A_log,
    float* __restrict__ beta, float* __restrict__ g) {
    extern __shared__ float bsm[];
    float* wbs = bsm;
    float* was = bsm + Dd*Hh;
    float* hst = bsm + 2*Dd*Hh;

    int tid = threadIdx.x;
    int hh  = tid & 15;
    int grp = tid >> 4;
    int row0 = blockIdx.x * BETAG_RPB;

    for (int i = tid; i < 8192; i += 256) {
        float4 vb = ((const float4*)Wb)[i & 4095];
        if (i < 4096) ((float4*)wbs)[i] = vb;
        else          ((float4*)was)[i - 4096] = ((const float4*)Wa)[i - 4096];
    }

    for (int p = 0; p < 2; p++) {
        int prow0 = row0 + p * BETAG_PASS;
        __syncthreads();
        for (int i = tid; i < 4096; i += 256)
            ((float4*)hst)[i] = ((const float4*)(h + (size_t)prow0 * Dd))[i];
        __syncthreads();

        float sb[BETAG_PASS], sa[BETAG_PASS];
        #pragma unroll
        for (int r = 0; r < BETAG_PASS; r++) { sb[r] = 0.0f; sa[r] = 0.0f; }

        #pragma unroll 4
        for (int j = 0; j < 64; j++) {
            int d = j*16 + grp;
            float wb = wbs[d*Hh + hh];
            float wa = was[d*Hh + hh];
            #pragma unroll
            for (int r = 0; r < BETAG_PASS; r++) {
                float hv = hst[r*Dd + d];
                sb[r] += hv * wb;
                sa[r] += hv * wa;
            }
        }
        __syncthreads();

        #pragma unroll
        for (int r = 0; r < BETAG_PASS; r++) {
            hst[(r<<9) + (grp<<4) + hh]       = sb[r];
            hst[(r<<9) + 256 + (grp<<4) + hh] = sa[r];
        }
        __syncthreads();

        #pragma unroll
        for (int u = 0; u < 2; u++) {
            int idx = tid + u*256;
            int r2    = idx >> 5;
            int which = (idx >> 4) & 1;
            int hh2   = idx & 15;
            const float* rp = hst + (r2<<9) + which*256 + hh2;
            float s = 0.0f;
            #pragma unroll
            for (int gg2 = 0; gg2 < 16; gg2++) s += rp[gg2*16];
            int row = prow0 + r2;
            if (which == 0) {
                beta[row*Hh + hh2] = 2.0f / (1.0f + expf(-s));
            } else {
                float xg = s + dt_bias[hh2];
                float sp = (xg > 15.0f) ? xg : log1pf(expf(xg));
                g[row*Hh + hh2] = -expf(A_log[hh2]) * sp;
            }
        }
    }
}

// ---------------------------------------------------------------------------
// Gated delta-rule scan (R11 winner)
// ---------------------------------------------------------------------------
__device__ __forceinline__ float scan_load(const float* __restrict__ q,
                                           const float* __restrict__ k,
                                           const float* __restrict__ v,
                                           const float* __restrict__ beta,
                                           const float* __restrict__ g,
                                           int b, int h, int t, int tid) {
    size_t off = ((size_t)(b*Tt + t)) * 1024 + h * 64;
    if (tid < 64)  return k[off + tid];
    if (tid < 128) return q[off + tid - 64];
    if (tid < 192) return v[off + tid - 128];
    if (tid == 192) return beta[(size_t)(b*Tt + t)*Hh + h];
    return g[(size_t)(b*Tt + t)*Hh + h];
}

__global__ __launch_bounds__(256) void scan_kernel(
    const float* __restrict__ q, const float* __restrict__ k, const float* __restrict__ v,
    const float* __restrict__ beta, const float* __restrict__ g,
    float* __restrict__ o, float* __restrict__ state_out) {
    int h = blockIdx.x, b = blockIdx.y;
    int tid = threadIdx.x;
    int c   = tid >> 2;
    int sub = tid & 3;

    __shared__ __align__(16) float sh[2][200];

    float S[16];
    #pragma unroll
    for (int r = 0; r < 16; r++) S[r] = 0.0f;

    float rv = (tid < 194) ? scan_load(q, k, v, beta, g, b, h, 0, tid) : 0.0f;

    for (int t = 0; t < Tt; t++) {
        float* buf = sh[t & 1];
        if (tid < 194) buf[tid] = rv;
        __syncthreads();
        if (t + 1 < Tt && tid < 194)
            rv = scan_load(q, k, v, beta, g, b, h, t + 1, tid);

        float eg = expf(buf[193]);
        float bt = buf[192];

        const float4* kp4 = (const float4*)(buf + sub*16);
        const float4* qp4 = (const float4*)(buf + 64 + sub*16);
        float kr[16], qr[16];
        #pragma unroll
        for (int rr = 0; rr < 4; rr++) {
            float4 kv4 = kp4[rr];
            kr[rr*4+0] = kv4.x; kr[rr*4+1] = kv4.y; kr[rr*4+2] = kv4.z; kr[rr*4+3] = kv4.w;
            float4 qv4 = qp4[rr];
            qr[rr*4+0] = qv4.x; qr[rr*4+1] = qv4.y; qr[rr*4+2] = qv4.z; qr[rr*4+3] = qv4.w;
        }

        float k0 = 0.0f, k1 = 0.0f, k2 = 0.0f, k3 = 0.0f;
        #pragma unroll
        for (int r4 = 0; r4 < 4; r4++) {
            S[4*r4+0] *= eg; k0 += kr[4*r4+0] * S[4*r4+0];
            S[4*r4+1] *= eg; k1 += kr[4*r4+1] * S[4*r4+1];
            S[4*r4+2] *= eg; k2 += kr[4*r4+2] * S[4*r4+2];
            S[4*r4+3] *= eg; k3 += kr[4*r4+3] * S[4*r4+3];
        }
        float kvp = (k0 + k1) + (k2 + k3);
        kvp += __shfl_xor_sync(0xffffffffu, kvp, 1);
        kvp += __shfl_xor_sync(0xffffffffu, kvp, 2);

        float delta = (buf[128 + c] - kvp) * bt;

        float o0 = 0.0f, o1 = 0.0f, o2 = 0.0f, o3 = 0.0f;
        #pragma unroll
        for (int r4 = 0; r4 < 4; r4++) {
            S[4*r4+0] += kr[4*r4+0] * delta; o0 += qr[4*r4+0] * S[4*r4+0];
            S[4*r4+1] += kr[4*r4+1] * delta; o1 += qr[4*r4+1] * S[4*r4+1];
            S[4*r4+2] += kr[4*r4+2] * delta; o2 += qr[4*r4+2] * S[4*r4+2];
            S[4*r4+3] += kr[4*r4+3] * delta; o3 += qr[4*r4+3] * S[4*r4+3];
        }
        float op = (o0 + o1) + (o2 + o3);
        op += __shfl_xor_sync(0xffffffffu, op, 1);
        op += __shfl_xor_sync(0xffffffffu, op, 2);
        if (sub == 0)
            o[((size_t)(b*Tt + t)*Hh + h) * DV + c] = op;
    }

    #pragma unroll
    for (int r = 0; r < 16; r++)
        state_out[((size_t)(b*Hh + h)*DK + sub*16 + r) * DV + c] = S[r];
}

// ---------------------------------------------------------------------------
// SwiGLU: actH = f16(silu(gy[:, :I]) * gy[:, I:]); gy fp16, 2 elems/thread
// ---------------------------------------------------------------------------
__global__ void swiglu_kernel(const __half* __restrict__ gy, __half* __restrict__ actH) {
    int idx2 = blockIdx.x * blockDim.x + threadIdx.x;   // over ROWS*II/2
    int row = idx2 / (II/2);
    int i   = (idx2 - row * (II/2)) * 2;
    float2 gate = __half22float2(*(const __half2*)(gy + (size_t)row * (2*II) + i));
    float2 y    = __half22float2(*(const __half2*)(gy + (size_t)row * (2*II) + II + i));
    float a0 = gate.x / (1.0f + expf(-gate.x)) * y.x;
    float a1 = gate.y / (1.0f + expf(-gate.y)) * y.y;
    *(__half2*)(actH + (size_t)row * II + i) = __floats2half2_rn(a0, a1);
}

// ---------------------------------------------------------------------------
// launch
// ---------------------------------------------------------------------------
extern "C" void kernel_launch(void* const* d_in, const int* in_sizes, int n_in,
                              void* d_out, int out_size) {
    const float* x           = (const float*)d_in[0];
    const float* attn_norm_w = (const float*)d_in[1];
    const float* Wq          = (const float*)d_in[2];
    const float* Wk          = (const float*)d_in[3];
    const float* Wv          = (const float*)d_in[4];
    const float* cq          = (const float*)d_in[5];
    const float* ck          = (const float*)d_in[6];
    const float* cv          = (const float*)d_in[7];
    const float* Wb          = (const float*)d_in[8];
    const float* Wa          = (const float*)d_in[9];
    const float* dt_bias     = (const float*)d_in[10];
    const float* A_log       = (const float*)d_in[11];
    const float* o_norm_w    = (const float*)d_in[12];
    const float* Wo          = (const float*)d_in[13];
    const float* mlp_norm_w  = (const float*)d_in[14];
    const float* Wg          = (const float*)d_in[15];
    const float* Wd          = (const float*)d_in[16];
    float* out = (float*)d_out;

    float *h, *qpre, *kpre, *vpre, *q, *k, *v, *beta, *gg, *o, *h2;
    __half *hH, *oH, *h3H, *gyH, *actH, *WqH, *WkH, *WvH, *WoH, *WgH, *WdH;
    cudaGetSymbolAddress((void**)&h,    g_h);
    cudaGetSymbolAddress((void**)&hH,   g_hH);
    cudaGetSymbolAddress((void**)&qpre, g_qpre);
    cudaGetSymbolAddress((void**)&kpre, g_kpre);
    cudaGetSymbolAddress((void**)&vpre, g_vpre);
    cudaGetSymbolAddress((void**)&q,    g_q);
    cudaGetSymbolAddress((void**)&k,    g_k);
    cudaGetSymbolAddress((void**)&v,    g_v);
    cudaGetSymbolAddress((void**)&beta, g_beta);
    cudaGetSymbolAddress((void**)&gg,   g_g);
    cudaGetSymbolAddress((void**)&o,    g_o);
    cudaGetSymbolAddress((void**)&oH,   g_oH);
    cudaGetSymbolAddress((void**)&h2,   g_h2);
    cudaGetSymbolAddress((void**)&h3H,  g_h3H);
    cudaGetSymbolAddress((void**)&gyH,  g_gyH);
    cudaGetSymbolAddress((void**)&actH, g_actH);
    cudaGetSymbolAddress((void**)&WqH,  g_WqH);
    cudaGetSymbolAddress((void**)&WkH,  g_WkH);
    cudaGetSymbolAddress((void**)&WvH,  g_WvH);
    cudaGetSymbolAddress((void**)&WoH,  g_WoH);
    cudaGetSymbolAddress((void**)&WgH,  g_WgH);
    cudaGetSymbolAddress((void**)&WdH,  g_WdH);

    cudaFuncSetAttribute(betag_kernel,
                         cudaFuncAttributeMaxDynamicSharedMemorySize, BETAG_SMEM_BYTES);
    cudaFuncSetAttribute(mma_gemm_kernel,
                         cudaFuncAttributeMaxDynamicSharedMemorySize, GEMM_DYN_BYTES);
    cudaFuncSetAttribute(mma_gemm_qkv_kernel,
                         cudaFuncAttributeMaxDynamicSharedMemorySize, GEMM_DYN_BYTES);
    cudaFuncSetAttribute(mma_gemm_h_kernel,
                         cudaFuncAttributeMaxDynamicSharedMemorySize, GEMM_DYN_BYTES);

    // 0. weights -> fp16
    {
        int nmax = Dd*2*II;
        int blocks = (nmax/2 + 255) / 256;
        dim3 gw(blocks, 6);
        wcvt_kernel<<<gw, 256>>>(Wq, WqH, Dd*Dd, Wk, WkH, Dd*Dd, Wv, WvH, Dd*Dd,
                                 Wo, WoH, Dd*Dd, Wg, WgH, Dd*2*II, Wd, WdH, II*Dd);
    }

    // 1. h = rmsnorm(x) -> fp32 (betag) + fp16 (GEMM)
    rmsnorm_kernel<<<ROWS, 256>>>(x, attn_norm_w, h, hH);

    // 2. q/k/v projections
    dim3 gqkv(Dd/GBN, ROWS/GBM, 3);
    mma_gemm_qkv_kernel<<<gqkv, 256, GEMM_DYN_BYTES>>>(hH, WqH, WkH, WvH,
                                                       qpre, kpre, vpre, Dd, Dd);

    // 3. conv + silu (+ fused l2norm for q,k)
    conv_fused3_kernel<<<dim3(ROWS, 3), 256>>>(qpre, cq, q, kpre, ck, k, vpre, cv, v);

    // 4. beta / g
    betag_kernel<<<BETAG_BLOCKS, 256, BETAG_SMEM_BYTES>>>(h, Wb, Wa, dt_bias, A_log, beta, gg);

    // 5. delta-rule scan
    scan_kernel<<<dim3(Hh, Bb), 256>>>(q, k, v, beta, gg, o, out + (size_t)ROWS*Dd);

    // 6. per-head output RMSNorm -> fp16
    o_rmsnorm_kernel<<<(ROWS*Hh)/8, 256>>>(o, o_norm_w, oH);

    // 7. attn projection + residual
    dim3 g1024(Dd/GBN, ROWS/GBM);
    mma_gemm_kernel<<<g1024, 256, GEMM_DYN_BYTES>>>(oH, WoH, x, h2, Dd, Dd);

    // 8. MLP
    rmsnorm_kernel<<<ROWS, 256>>>(h2, mlp_norm_w, nullptr, h3H);
    dim3 gwg((2*II)/GBN, ROWS/GBM);
    mma_gemm_h_kernel<<<gwg, 256, GEMM_DYN_BYTES>>>(h3H, WgH, gyH, 2*II, Dd);
    swiglu_kernel<<<(ROWS*II/2)/256, 256>>>(gyH, actH);
    mma_gemm_kernel<<<g1024, 256, GEMM_DYN_BYTES>>>(actH, WdH, h2, out, Dd, II);
}